// round 13
// baseline (speedup 1.0000x reference)
#include <cuda_runtime.h>
#include <math.h>
#include <float.h>
#include <limits.h>

#define NPTS   1000
#define BATCH  2
#define NROWS  (BATCH*NPTS)
#define KNN    8
#define NEDGE_PB (NPTS*KNN)
#define NEDGES (BATCH*NEDGE_PB)
#define PAIRS  (NPTS*(NPTS-1)/2)
#define XCAT   672

// ---------------- scratch (static device globals; no allocation) ----------
__device__ float g_d2[BATCH*NPTS*NPTS];    // 8 MB pairwise sq-dist
__device__ int   g_idx[NROWS*KNN];
__device__ float g_sq[NROWS];
__device__ float g_xcat[NROWS*XCAT];       // [x1 | x2 | x3]
__device__ float g_uv[NROWS*512];          // fused [u | v], ld = 2H (max 512)
__device__ float g_wcat[128*512];          // [wdiff | w1b], C x 2H
__device__ float g_bcat[512];              // [b1 | 0]
__device__ float g_h1[NROWS*256];
__device__ float g_sf[NROWS*128];
__device__ float g_gmax[BATCH*128];
__device__ float g_hg[BATCH*128];
__device__ float g_hi[NROWS*128];
__device__ float g_hj[NROWS*128];

// ---------------- squared norms -------------------------------------------
__global__ void sq_kernel(const float* __restrict__ x, int lda, int C) {
    int row = blockIdx.x * 8 + (threadIdx.x >> 5);
    int lane = threadIdx.x & 31;
    if (row >= NROWS) return;
    const float* xr = x + (size_t)row * lda;
    float s = 0.f;
    for (int c = lane; c < C; c += 32) { float v = xr[c]; s += v * v; }
    #pragma unroll
    for (int o = 16; o; o >>= 1) s += __shfl_down_sync(0xffffffffu, s, o);
    if (!lane) g_sq[row] = s;
}

// ---------------- pairwise d2 = sq_i + sq_j - 2*dot (tiled, LDS.128) ------
__global__ __launch_bounds__(256) void d2_kernel(const float* __restrict__ x, int lda, int C) {
    int b = blockIdx.z;
    int i0 = blockIdx.y * 64, j0 = blockIdx.x * 64;
    __shared__ __align__(16) float As[16][68], Bs[16][68];
    int tid = threadIdx.x, tx = tid % 16, ty = tid / 16;
    float acc[4][4] = {};
    const float* xb = x + (size_t)b * NPTS * lda;
    for (int k0 = 0; k0 < C; k0 += 16) {
        #pragma unroll
        for (int l0 = 0; l0 < 1024; l0 += 256) {
            int l = l0 + tid;
            int r = l >> 4, kk = l & 15;
            int c = k0 + kk;
            int ri = i0 + r, rj = j0 + r;
            As[kk][r] = (ri < NPTS && c < C) ? xb[(size_t)ri * lda + c] : 0.f;
            Bs[kk][r] = (rj < NPTS && c < C) ? xb[(size_t)rj * lda + c] : 0.f;
        }
        __syncthreads();
        #pragma unroll
        for (int kk = 0; kk < 16; kk++) {
            float4 a4 = *(const float4*)&As[kk][ty*4];
            float4 b4 = *(const float4*)&Bs[kk][tx*4];
            float a[4] = {a4.x, a4.y, a4.z, a4.w};
            float bb[4] = {b4.x, b4.y, b4.z, b4.w};
            #pragma unroll
            for (int qi = 0; qi < 4; qi++)
                #pragma unroll
                for (int qj = 0; qj < 4; qj++)
                    acc[qi][qj] += a[qi] * bb[qj];
        }
        __syncthreads();
    }
    #pragma unroll
    for (int qi = 0; qi < 4; qi++) {
        int i = i0 + ty*4 + qi;
        if (i >= NPTS) continue;
        #pragma unroll
        for (int qj = 0; qj < 4; qj++) {
            int j = j0 + tx*4 + qj;
            if (j >= NPTS) continue;
            g_d2[(size_t)b*NPTS*NPTS + (size_t)i*NPTS + j] =
                g_sq[b*NPTS+i] + g_sq[b*NPTS+j] - 2.f * acc[qi][qj];
        }
    }
}

// ---------------- top-8 smallest per row: one warp per row ----------------
__global__ __launch_bounds__(256) void topk_kernel() {
    __shared__ float cv[8][32][8];
    __shared__ int   ci[8][32][8];
    int w = threadIdx.x >> 5, lane = threadIdx.x & 31;
    int row = blockIdx.x * 8 + w;
    int b = row / NPTS, i = row % NPTS;
    const float* drow = g_d2 + (size_t)b*NPTS*NPTS + (size_t)i*NPTS;

    float v[8]; int id[8];
    #pragma unroll
    for (int s = 0; s < 8; s++) { v[s] = FLT_MAX; id[s] = INT_MAX; }
    for (int j = lane; j < NPTS; j += 32) {
        float d = drow[j];
        if (d < v[7]) {
            v[7] = d; id[7] = j;
            #pragma unroll
            for (int s = 7; s > 0; s--) {
                if (v[s] < v[s-1] || (v[s] == v[s-1] && id[s] < id[s-1])) {
                    float tv = v[s]; v[s] = v[s-1]; v[s-1] = tv;
                    int   ti = id[s]; id[s] = id[s-1]; id[s-1] = ti;
                }
            }
        }
    }
    #pragma unroll
    for (int s = 0; s < 8; s++) { cv[w][lane][s] = v[s]; ci[w][lane][s] = id[s]; }
    __syncwarp();

    int h = 0;
    for (int k = 0; k < 8; k++) {
        float bv = (h < 8) ? cv[w][lane][h] : FLT_MAX;
        int   bi = (h < 8) ? ci[w][lane][h] : INT_MAX;
        int   bl = lane;
        #pragma unroll
        for (int o = 16; o; o >>= 1) {
            float ov = __shfl_xor_sync(0xffffffffu, bv, o);
            int   oi = __shfl_xor_sync(0xffffffffu, bi, o);
            int   ol = __shfl_xor_sync(0xffffffffu, bl, o);
            if (ov < bv || (ov == bv && oi < bi)) { bv = ov; bi = oi; bl = ol; }
        }
        if (lane == 0) g_idx[row*KNN + k] = bi;
        if (lane == bl) h++;
    }
}

// ---------------- wcat = [w1[:C]-w1[C:] | w1[C:]], bcat = [b1 | 0] --------
__global__ void wprep_kernel(const float* __restrict__ w1,
                             const float* __restrict__ b1, int C, int H) {
    int l = blockIdx.x * 256 + threadIdx.x;
    int H2 = 2 * H;
    int tot = C * H2;
    if (l < tot) {
        int c = l / H2, h = l % H2;
        float v;
        if (h < H) v = w1[(size_t)c*H + h] - w1[(size_t)(C + c)*H + h];
        else       v = w1[(size_t)(C + c)*H + (h - H)];
        g_wcat[l] = v;
    }
    if (l < H2) g_bcat[l] = (l < H) ? b1[l] : 0.f;
}

// ---------------- generic tiled GEMM: C = act(A@W + bias), LDS.128 --------
__global__ __launch_bounds__(256) void gemm_kernel(
    const float* __restrict__ A, int lda,
    const float* __restrict__ W,
    const float* __restrict__ bias,
    float* __restrict__ Cmat, int ldc,
    int M, int K, int N, int relu)
{
    __shared__ __align__(16) float As[16][68], Ws[16][68];
    int m0 = blockIdx.x * 64, n0 = blockIdx.y * 64;
    int tid = threadIdx.x, tx = tid % 16, ty = tid / 16;
    float acc[4][4] = {};
    for (int k0 = 0; k0 < K; k0 += 16) {
        #pragma unroll
        for (int l0 = 0; l0 < 1024; l0 += 256) {
            int l = l0 + tid;
            int r = l >> 4, kk = l & 15;
            int row = m0 + r, c = k0 + kk;
            As[kk][r] = (row < M && c < K) ? A[(size_t)row * lda + c] : 0.f;
        }
        #pragma unroll
        for (int l0 = 0; l0 < 1024; l0 += 256) {
            int l = l0 + tid;
            int kk = l >> 6, n = l & 63;
            int row = k0 + kk, col = n0 + n;
            Ws[kk][n] = (row < K && col < N) ? W[(size_t)row * N + col] : 0.f;
        }
        __syncthreads();
        #pragma unroll
        for (int kk = 0; kk < 16; kk++) {
            float4 a4 = *(const float4*)&As[kk][ty*4];
            float4 b4 = *(const float4*)&Ws[kk][tx*4];
            float a[4] = {a4.x, a4.y, a4.z, a4.w};
            float bb[4] = {b4.x, b4.y, b4.z, b4.w};
            #pragma unroll
            for (int qi = 0; qi < 4; qi++)
                #pragma unroll
                for (int qj = 0; qj < 4; qj++)
                    acc[qi][qj] += a[qi] * bb[qj];
        }
        __syncthreads();
    }
    #pragma unroll
    for (int qi = 0; qi < 4; qi++) {
        int row = m0 + ty*4 + qi;
        if (row >= M) continue;
        #pragma unroll
        for (int qj = 0; qj < 4; qj++) {
            int col = n0 + tx*4 + qj;
            if (col >= N) continue;
            float v = acc[qi][qj];
            if (bias) v += bias[col];
            if (relu) v = fmaxf(v, 0.f);
            Cmat[(size_t)row * ldc + col] = v;
        }
    }
}

// ---------------- small edge GEMM (conv1): 64x64 tile ---------------------
__global__ __launch_bounds__(256) void edge_gemm_kernel(
    const float* __restrict__ uv, int ld,
    const float* __restrict__ w2, const float* __restrict__ b2,
    float* __restrict__ out, int ldo, int H, int Cout)
{
    __shared__ int pt_s[64], nb_s[64];
    __shared__ __align__(16) float As[16][68], Ws[16][68];
    __shared__ float Rs[64][65];
    int tid = threadIdx.x;
    int e0 = blockIdx.x * 64;
    int n0 = blockIdx.y * 64;
    if (tid < 64) {
        int e = e0 + tid;
        int b = e / NEDGE_PB;
        int eb = e % NEDGE_PB;
        int i = eb / KNN, k = eb % KNN;
        int pt = b * NPTS + i;
        pt_s[tid] = pt;
        nb_s[tid] = b * NPTS + g_idx[pt*KNN + k];
    }
    __syncthreads();
    int tx = tid % 16, ty = tid / 16;
    float acc[4][4] = {};
    for (int k0 = 0; k0 < H; k0 += 16) {
        #pragma unroll
        for (int l0 = 0; l0 < 1024; l0 += 256) {
            int l = l0 + tid;
            int r = l >> 4, kk = l & 15;
            int h = k0 + kk;
            float a = uv[(size_t)pt_s[r]*ld + h] + uv[(size_t)nb_s[r]*ld + H + h];
            As[kk][r] = fmaxf(a, 0.f);
        }
        #pragma unroll
        for (int l0 = 0; l0 < 1024; l0 += 256) {
            int l = l0 + tid;
            int kk = l >> 6, n = l & 63;
            int col = n0 + n;
            Ws[kk][n] = (col < Cout) ? w2[(size_t)(k0+kk)*Cout + col] : 0.f;
        }
        __syncthreads();
        #pragma unroll
        for (int kk = 0; kk < 16; kk++) {
            float4 a4 = *(const float4*)&As[kk][ty*4];
            float4 b4 = *(const float4*)&Ws[kk][tx*4];
            float a[4] = {a4.x, a4.y, a4.z, a4.w};
            float bb[4] = {b4.x, b4.y, b4.z, b4.w};
            #pragma unroll
            for (int qi = 0; qi < 4; qi++)
                #pragma unroll
                for (int qj = 0; qj < 4; qj++)
                    acc[qi][qj] += a[qi] * bb[qj];
        }
        __syncthreads();
    }
    #pragma unroll
    for (int qi = 0; qi < 4; qi++)
        #pragma unroll
        for (int qj = 0; qj < 4; qj++)
            Rs[ty*4+qi][tx*4+qj] = acc[qi][qj];
    __syncthreads();
    int pt0 = pt_s[0];
    for (int l = tid; l < 512; l += 256) {
        int pl = l >> 6, c = l & 63;
        int col = n0 + c;
        if (col < Cout) {
            float m = Rs[pl*8][c];
            #pragma unroll
            for (int r = 1; r < 8; r++) m = fmaxf(m, Rs[pl*8 + r][c]);
            out[(size_t)(pt0 + pl)*ldo + col] = m + b2[col];
        }
    }
}

// ---------------- wide edge GEMM: 64 edges x 128 cols, 4x8/thread ---------
// Same 64-row A-gather as the proven 64x64 kernel; N-tile doubled so the
// gathered A traffic and k-loop overhead amortize over 2x the FFMA work.
__global__ __launch_bounds__(256) void edge_gemm64x128_kernel(
    const float* __restrict__ uv, int ld,
    const float* __restrict__ w2, const float* __restrict__ b2,
    float* __restrict__ out, int ldo, int H, int Cout)
{
    __shared__ int pt_s[64], nb_s[64];
    __shared__ __align__(16) float As[16][68], Ws[16][132];
    __shared__ float Rs[64][129];
    int tid = threadIdx.x;
    int e0 = blockIdx.x * 64;
    int n0 = blockIdx.y * 128;
    if (tid < 64) {
        int e = e0 + tid;
        int b = e / NEDGE_PB;
        int eb = e % NEDGE_PB;
        int i = eb / KNN, k = eb % KNN;
        int pt = b * NPTS + i;
        pt_s[tid] = pt;
        nb_s[tid] = b * NPTS + g_idx[pt*KNN + k];
    }
    __syncthreads();
    int tx = tid % 16, ty = tid / 16;
    float acc[4][8] = {};
    for (int k0 = 0; k0 < H; k0 += 16) {
        // A tile: relu(u_i + v_j), 64 rows x 16 k (identical to 64x64 path)
        #pragma unroll
        for (int l0 = 0; l0 < 1024; l0 += 256) {
            int l = l0 + tid;
            int r = l >> 4, kk = l & 15;
            int h = k0 + kk;
            float a = uv[(size_t)pt_s[r]*ld + h] + uv[(size_t)nb_s[r]*ld + H + h];
            As[kk][r] = fmaxf(a, 0.f);
        }
        // W tile: 16 k x 128 cols (no bounds checks: Cout % 128 == 0)
        #pragma unroll
        for (int l0 = 0; l0 < 2048; l0 += 256) {
            int l = l0 + tid;
            int kk = l >> 7, n = l & 127;
            Ws[kk][n] = w2[(size_t)(k0 + kk)*Cout + n0 + n];
        }
        __syncthreads();
        #pragma unroll
        for (int kk = 0; kk < 16; kk++) {
            float4 a4 = *(const float4*)&As[kk][ty*4];
            float4 b0 = *(const float4*)&Ws[kk][tx*8];
            float4 b1 = *(const float4*)&Ws[kk][tx*8 + 4];
            float a[4]  = {a4.x, a4.y, a4.z, a4.w};
            float bb[8] = {b0.x, b0.y, b0.z, b0.w, b1.x, b1.y, b1.z, b1.w};
            #pragma unroll
            for (int qi = 0; qi < 4; qi++)
                #pragma unroll
                for (int qj = 0; qj < 8; qj++)
                    acc[qi][qj] += a[qi] * bb[qj];
        }
        __syncthreads();
    }
    #pragma unroll
    for (int qi = 0; qi < 4; qi++)
        #pragma unroll
        for (int qj = 0; qj < 8; qj++)
            Rs[ty*4+qi][tx*8+qj] = acc[qi][qj];
    __syncthreads();
    int pt0 = pt_s[0];
    for (int l = tid; l < 1024; l += 256) {
        int pl = l >> 7, c = l & 127;
        int col = n0 + c;
        float m = Rs[pl*8][c];
        #pragma unroll
        for (int r = 1; r < 8; r++) m = fmaxf(m, Rs[pl*8 + r][c]);
        out[(size_t)(pt0 + pl)*ldo + col] = m + b2[col];
    }
}

// ---------------- global max pool over N ----------------------------------
__global__ void gmax_kernel() {
    int b = blockIdx.x, tid = threadIdx.x;
    int c = tid & 127, part = tid >> 7;
    __shared__ float sm[512];
    float m = -FLT_MAX;
    int n0 = part * (NPTS/4), n1 = n0 + NPTS/4;
    for (int n = n0; n < n1; n++)
        m = fmaxf(m, g_sf[(size_t)(b*NPTS + n)*128 + c]);
    sm[tid] = m;
    __syncthreads();
    if (tid < 128)
        g_gmax[b*128 + c] = fmaxf(fmaxf(sm[tid], sm[tid+128]),
                                  fmaxf(sm[tid+256], sm[tid+384]));
}

// ---------------- hg = g @ ec_w1[256:384] + ec_b1 -------------------------
__global__ void hg_kernel(const float* __restrict__ ecw1, const float* __restrict__ ecb1) {
    int b = blockIdx.x, h = threadIdx.x;
    float acc = ecb1[h];
    for (int c = 0; c < 128; c++)
        acc += g_gmax[b*128 + c] * ecw1[(size_t)(256 + c)*128 + h];
    g_hg[b*128 + h] = acc;
}

// ---------------- pair kernel ---------------------------------------------
__global__ __launch_bounds__(256) void pair_kernel(
    const float* __restrict__ ecw2, const float* __restrict__ ecb2,
    float* __restrict__ out)
{
    int tj = blockIdx.x, ti = blockIdx.y, b = blockIdx.z;
    if (ti > tj) return;
    int i0 = ti * 64, j0 = tj * 64;
    __shared__ __align__(16) float As[32][68], Bs[32][68];
    __shared__ float Ww[32];
    int tid = threadIdx.x, tx = tid % 16, ty = tid / 16;
    float acc[4][4] = {};
    for (int h0 = 0; h0 < 128; h0 += 32) {
        #pragma unroll
        for (int l0 = 0; l0 < 2048; l0 += 256) {
            int l = l0 + tid;
            int r = l >> 5, kk = l & 31;
            int ii = i0 + r, jj = j0 + r;
            As[kk][r] = (ii < NPTS)
                ? g_hi[(size_t)(b*NPTS + ii)*128 + h0 + kk] + g_hg[b*128 + h0 + kk]
                : 0.f;
            Bs[kk][r] = (jj < NPTS)
                ? g_hj[(size_t)(b*NPTS + jj)*128 + h0 + kk]
                : 0.f;
        }
        if (tid < 32) Ww[tid] = ecw2[h0 + tid];
        __syncthreads();
        #pragma unroll
        for (int kk = 0; kk < 32; kk++) {
            float w = Ww[kk];
            float4 a4 = *(const float4*)&As[kk][ty*4];
            float4 b4 = *(const float4*)&Bs[kk][tx*4];
            float a[4] = {a4.x, a4.y, a4.z, a4.w};
            float bb[4] = {b4.x, b4.y, b4.z, b4.w};
            #pragma unroll
            for (int qi = 0; qi < 4; qi++)
                #pragma unroll
                for (int qj = 0; qj < 4; qj++)
                    acc[qi][qj] += fmaxf(a[qi] + bb[qj], 0.f) * w;
        }
        __syncthreads();
    }
    float bias = ecb2[0];
    #pragma unroll
    for (int qi = 0; qi < 4; qi++) {
        int i = i0 + ty*4 + qi;
        #pragma unroll
        for (int qj = 0; qj < 4; qj++) {
            int j = j0 + tx*4 + qj;
            if (j < NPTS && i < j) {
                float val = acc[qi][qj] + bias;
                int p = i*(2*NPTS - i - 1)/2 + (j - i - 1);
                out[(size_t)b*PAIRS + p] = 1.f / (1.f + __expf(-val));
                out[(size_t)(BATCH + b)*PAIRS + p] = val;
            }
        }
    }
}

// ---------------- host side -----------------------------------------------
static void run_conv(const float* xin, int lda, int C, int H, int Cout, int outoff,
                     const float* w1, const float* b1, const float* w2, const float* b2,
                     float* dxcat, float* duv, float* dwcat, float* dbcat)
{
    sq_kernel<<<(NROWS + 7)/8, 256>>>(xin, lda, C);
    dim3 gd2((NPTS + 63)/64, (NPTS + 63)/64, BATCH);
    d2_kernel<<<gd2, 256>>>(xin, lda, C);
    topk_kernel<<<NROWS/8, 256>>>();
    int H2 = 2 * H;
    int tot = C * H2;
    wprep_kernel<<<(tot + 255)/256, 256>>>(w1, b1, C, H);
    // uv = x @ wcat + bcat  (M=NROWS, K=C, N=2H)
    dim3 ggu((NROWS + 63)/64, (H2 + 63)/64);
    gemm_kernel<<<ggu, 256>>>(xin, lda, dwcat, dbcat, duv, H2, NROWS, C, H2, 0);
    if ((Cout % 128) == 0) {
        dim3 ge(NEDGES/64, Cout/128);
        edge_gemm64x128_kernel<<<ge, 256>>>(duv, H2, w2, b2, dxcat + outoff, XCAT, H, Cout);
    } else {
        dim3 ge(NEDGES/64, (Cout + 63)/64);
        edge_gemm_kernel<<<ge, 256>>>(duv, H2, w2, b2, dxcat + outoff, XCAT, H, Cout);
    }
}

extern "C" void kernel_launch(void* const* d_in, const int* in_sizes, int n_in,
                              void* d_out, int out_size)
{
    const float* pos   = (const float*)d_in[0];
    const float* c1w1  = (const float*)d_in[1];
    const float* c1b1  = (const float*)d_in[2];
    const float* c1w2  = (const float*)d_in[3];
    const float* c1b2  = (const float*)d_in[4];
    const float* c2w1  = (const float*)d_in[5];
    const float* c2b1  = (const float*)d_in[6];
    const float* c2w2  = (const float*)d_in[7];
    const float* c2b2  = (const float*)d_in[8];
    const float* c3w1  = (const float*)d_in[9];
    const float* c3b1  = (const float*)d_in[10];
    const float* c3w2  = (const float*)d_in[11];
    const float* c3b2  = (const float*)d_in[12];
    const float* smw1  = (const float*)d_in[13];
    const float* smb1  = (const float*)d_in[14];
    const float* smw2  = (const float*)d_in[15];
    const float* smb2  = (const float*)d_in[16];
    const float* ecw1  = (const float*)d_in[17];
    const float* ecb1  = (const float*)d_in[18];
    const float* ecw2  = (const float*)d_in[19];
    const float* ecb2  = (const float*)d_in[20];
    float* out = (float*)d_out;

    float *dxcat, *duv, *dwcat, *dbcat, *dh1, *dsf, *dhi, *dhj;
    cudaGetSymbolAddress((void**)&dxcat, g_xcat);
    cudaGetSymbolAddress((void**)&duv,   g_uv);
    cudaGetSymbolAddress((void**)&dwcat, g_wcat);
    cudaGetSymbolAddress((void**)&dbcat, g_bcat);
    cudaGetSymbolAddress((void**)&dh1,   g_h1);
    cudaGetSymbolAddress((void**)&dsf,   g_sf);
    cudaGetSymbolAddress((void**)&dhi,   g_hi);
    cudaGetSymbolAddress((void**)&dhj,   g_hj);

    // Three dynamic edge convs, outputs concatenated into g_xcat
    run_conv(pos,        3,    3,   16,  32,   0,   c1w1, c1b1, c1w2, c1b2, dxcat, duv, dwcat, dbcat);
    run_conv(dxcat + 0,  XCAT, 32,  64,  128, 32,   c2w1, c2b1, c2w2, c2b2, dxcat, duv, dwcat, dbcat);
    run_conv(dxcat + 32, XCAT, 128, 256, 512, 160,  c3w1, c3b1, c3w2, c3b2, dxcat, duv, dwcat, dbcat);

    // sf = MLP(xcat): 672 -> 256 (relu) -> 128
    {
        dim3 g1((NROWS + 63)/64, (256 + 63)/64);
        gemm_kernel<<<g1, 256>>>(dxcat, XCAT, smw1, smb1, dh1, 256, NROWS, XCAT, 256, 1);
        dim3 g2((NROWS + 63)/64, (128 + 63)/64);
        gemm_kernel<<<g2, 256>>>(dh1, 256, smw2, smb2, dsf, 128, NROWS, 256, 128, 0);
    }

    // global max pool
    gmax_kernel<<<BATCH, 512>>>();

    // hi = sf @ ec_w1[:128], hj = sf @ ec_w1[128:256], hg = g @ ec_w1[256:] + b1
    {
        dim3 g3((NROWS + 63)/64, (128 + 63)/64);
        gemm_kernel<<<g3, 256>>>(dsf, 128, ecw1,           (const float*)nullptr, dhi, 128, NROWS, 128, 128, 0);
        gemm_kernel<<<g3, 256>>>(dsf, 128, ecw1 + 128*128, (const float*)nullptr, dhj, 128, NROWS, 128, 128, 0);
        hg_kernel<<<BATCH, 128>>>(ecw1, ecb1);
    }

    // pairwise output
    {
        dim3 gp((NPTS + 63)/64, (NPTS + 63)/64, BATCH);
        pair_kernel<<<gp, 256>>>(ecw2, ecb2, out);
    }
    (void)in_sizes; (void)n_in; (void)out_size;
}

// round 14
// speedup vs baseline: 1.2895x; 1.2895x over previous
#include <cuda_runtime.h>
#include <math.h>
#include <float.h>

#define NPTS   1000
#define BATCH  2
#define NROWS  (BATCH*NPTS)
#define KNN    8
#define NEDGE_PB (NPTS*KNN)
#define NEDGES (BATCH*NEDGE_PB)
#define PAIRS  (NPTS*(NPTS-1)/2)
#define XCAT   672

// ---------------- scratch (static device globals; no allocation) ----------
__device__ float g_d2[BATCH*NPTS*NPTS];    // 8 MB pairwise sq-dist
__device__ int   g_idx[NROWS*KNN];
__device__ float g_sq[NROWS];
__device__ float g_xcat[NROWS*XCAT];       // [x1 | x2 | x3]
__device__ float g_uv[NROWS*512];          // fused [u | v], ld = 2H (max 512)
__device__ float g_wcat[128*512];          // [wdiff | w1b], C x 2H
__device__ float g_bcat[512];              // [b1 | 0]
__device__ float g_h1[NROWS*256];
__device__ float g_sf[NROWS*128];
__device__ float g_gmax[BATCH*128];
__device__ float g_hg[BATCH*128];
__device__ float g_hi[NROWS*128];
__device__ float g_hj[NROWS*128];

// ---------------- tf32 helper ---------------------------------------------
__device__ __forceinline__ unsigned f2tf32(float f) {
    unsigned u;
    asm("cvt.rna.tf32.f32 %0, %1;" : "=r"(u) : "f"(f));
    return u;
}

// ---------------- squared norms -------------------------------------------
__global__ void sq_kernel(const float* __restrict__ x, int lda, int C) {
    int row = blockIdx.x * 8 + (threadIdx.x >> 5);
    int lane = threadIdx.x & 31;
    if (row >= NROWS) return;
    const float* xr = x + (size_t)row * lda;
    float s = 0.f;
    for (int c = lane; c < C; c += 32) { float v = xr[c]; s += v * v; }
    #pragma unroll
    for (int o = 16; o; o >>= 1) s += __shfl_down_sync(0xffffffffu, s, o);
    if (!lane) g_sq[row] = s;
}

// ---------------- pairwise d2 = sq_i + sq_j - 2*dot (tiled, LDS.128) ------
__global__ __launch_bounds__(256) void d2_kernel(const float* __restrict__ x, int lda, int C) {
    int b = blockIdx.z;
    int i0 = blockIdx.y * 64, j0 = blockIdx.x * 64;
    __shared__ __align__(16) float As[16][68], Bs[16][68];
    int tid = threadIdx.x, tx = tid % 16, ty = tid / 16;
    float acc[4][4] = {};
    const float* xb = x + (size_t)b * NPTS * lda;
    for (int k0 = 0; k0 < C; k0 += 16) {
        #pragma unroll
        for (int l0 = 0; l0 < 1024; l0 += 256) {
            int l = l0 + tid;
            int r = l >> 4, kk = l & 15;
            int c = k0 + kk;
            int ri = i0 + r, rj = j0 + r;
            As[kk][r] = (ri < NPTS && c < C) ? xb[(size_t)ri * lda + c] : 0.f;
            Bs[kk][r] = (rj < NPTS && c < C) ? xb[(size_t)rj * lda + c] : 0.f;
        }
        __syncthreads();
        #pragma unroll
        for (int kk = 0; kk < 16; kk++) {
            float4 a4 = *(const float4*)&As[kk][ty*4];
            float4 b4 = *(const float4*)&Bs[kk][tx*4];
            float a[4] = {a4.x, a4.y, a4.z, a4.w};
            float bb[4] = {b4.x, b4.y, b4.z, b4.w};
            #pragma unroll
            for (int qi = 0; qi < 4; qi++)
                #pragma unroll
                for (int qj = 0; qj < 4; qj++)
                    acc[qi][qj] += a[qi] * bb[qj];
        }
        __syncthreads();
    }
    #pragma unroll
    for (int qi = 0; qi < 4; qi++) {
        int i = i0 + ty*4 + qi;
        if (i >= NPTS) continue;
        #pragma unroll
        for (int qj = 0; qj < 4; qj++) {
            int j = j0 + tx*4 + qj;
            if (j >= NPTS) continue;
            g_d2[(size_t)b*NPTS*NPTS + (size_t)i*NPTS + j] =
                g_sq[b*NPTS+i] + g_sq[b*NPTS+j] - 2.f * acc[qi][qj];
        }
    }
}

// ---------------- top-8 smallest per row ----------------------------------
__global__ void topk_kernel() {
    int row = blockIdx.x;
    int b = row / NPTS, i = row % NPTS;
    const float* drow = g_d2 + (size_t)b*NPTS*NPTS + (size_t)i*NPTS;
    __shared__ float vals[NPTS];
    __shared__ float rv[128];
    __shared__ int   ri[128];
    int tid = threadIdx.x;
    for (int l = tid; l < NPTS; l += 128) vals[l] = drow[l];
    __syncthreads();
    for (int k = 0; k < KNN; k++) {
        float bv = FLT_MAX; int bi = NPTS;
        for (int l = tid; l < NPTS; l += 128) {
            float v = vals[l];
            if (v < bv) { bv = v; bi = l; }
        }
        rv[tid] = bv; ri[tid] = bi;
        __syncthreads();
        for (int s = 64; s > 0; s >>= 1) {
            if (tid < s) {
                if (rv[tid+s] < rv[tid] ||
                    (rv[tid+s] == rv[tid] && ri[tid+s] < ri[tid])) {
                    rv[tid] = rv[tid+s]; ri[tid] = ri[tid+s];
                }
            }
            __syncthreads();
        }
        if (tid == 0) { g_idx[row*KNN + k] = ri[0]; vals[ri[0]] = FLT_MAX; }
        __syncthreads();
    }
}

// ---------------- wcat = [w1[:C]-w1[C:] | w1[C:]], bcat = [b1 | 0] --------
__global__ void wprep_kernel(const float* __restrict__ w1,
                             const float* __restrict__ b1, int C, int H) {
    int l = blockIdx.x * 256 + threadIdx.x;
    int H2 = 2 * H;
    int tot = C * H2;
    if (l < tot) {
        int c = l / H2, h = l % H2;
        float v;
        if (h < H) v = w1[(size_t)c*H + h] - w1[(size_t)(C + c)*H + h];
        else       v = w1[(size_t)(C + c)*H + (h - H)];
        g_wcat[l] = v;
    }
    if (l < H2) g_bcat[l] = (l < H) ? b1[l] : 0.f;
}

// ---------------- generic tiled GEMM: C = act(A@W + bias), LDS.128 --------
__global__ __launch_bounds__(256) void gemm_kernel(
    const float* __restrict__ A, int lda,
    const float* __restrict__ W,
    const float* __restrict__ bias,
    float* __restrict__ Cmat, int ldc,
    int M, int K, int N, int relu)
{
    __shared__ __align__(16) float As[16][68], Ws[16][68];
    int m0 = blockIdx.x * 64, n0 = blockIdx.y * 64;
    int tid = threadIdx.x, tx = tid % 16, ty = tid / 16;
    float acc[4][4] = {};
    for (int k0 = 0; k0 < K; k0 += 16) {
        #pragma unroll
        for (int l0 = 0; l0 < 1024; l0 += 256) {
            int l = l0 + tid;
            int r = l >> 4, kk = l & 15;
            int row = m0 + r, c = k0 + kk;
            As[kk][r] = (row < M && c < K) ? A[(size_t)row * lda + c] : 0.f;
        }
        #pragma unroll
        for (int l0 = 0; l0 < 1024; l0 += 256) {
            int l = l0 + tid;
            int kk = l >> 6, n = l & 63;
            int row = k0 + kk, col = n0 + n;
            Ws[kk][n] = (row < K && col < N) ? W[(size_t)row * N + col] : 0.f;
        }
        __syncthreads();
        #pragma unroll
        for (int kk = 0; kk < 16; kk++) {
            float4 a4 = *(const float4*)&As[kk][ty*4];
            float4 b4 = *(const float4*)&Ws[kk][tx*4];
            float a[4] = {a4.x, a4.y, a4.z, a4.w};
            float bb[4] = {b4.x, b4.y, b4.z, b4.w};
            #pragma unroll
            for (int qi = 0; qi < 4; qi++)
                #pragma unroll
                for (int qj = 0; qj < 4; qj++)
                    acc[qi][qj] += a[qi] * bb[qj];
        }
        __syncthreads();
    }
    #pragma unroll
    for (int qi = 0; qi < 4; qi++) {
        int row = m0 + ty*4 + qi;
        if (row >= M) continue;
        #pragma unroll
        for (int qj = 0; qj < 4; qj++) {
            int col = n0 + tx*4 + qj;
            if (col >= N) continue;
            float v = acc[qi][qj];
            if (bias) v += bias[col];
            if (relu) v = fmaxf(v, 0.f);
            Cmat[(size_t)row * ldc + col] = v;
        }
    }
}

// ---------------- edge GEMM (fp32 FFMA, conv1/conv2): 64x64 tile ----------
__global__ __launch_bounds__(256) void edge_gemm_kernel(
    const float* __restrict__ uv, int ld,
    const float* __restrict__ w2, const float* __restrict__ b2,
    float* __restrict__ out, int ldo, int H, int Cout)
{
    __shared__ int pt_s[64], nb_s[64];
    __shared__ __align__(16) float As[16][68], Ws[16][68];
    __shared__ float Rs[64][65];
    int tid = threadIdx.x;
    int e0 = blockIdx.x * 64;
    int n0 = blockIdx.y * 64;
    if (tid < 64) {
        int e = e0 + tid;
        int b = e / NEDGE_PB;
        int eb = e % NEDGE_PB;
        int i = eb / KNN, k = eb % KNN;
        int pt = b * NPTS + i;
        pt_s[tid] = pt;
        nb_s[tid] = b * NPTS + g_idx[pt*KNN + k];
    }
    __syncthreads();
    int tx = tid % 16, ty = tid / 16;
    float acc[4][4] = {};
    for (int k0 = 0; k0 < H; k0 += 16) {
        #pragma unroll
        for (int l0 = 0; l0 < 1024; l0 += 256) {
            int l = l0 + tid;
            int r = l >> 4, kk = l & 15;
            int h = k0 + kk;
            float a = uv[(size_t)pt_s[r]*ld + h] + uv[(size_t)nb_s[r]*ld + H + h];
            As[kk][r] = fmaxf(a, 0.f);
        }
        #pragma unroll
        for (int l0 = 0; l0 < 1024; l0 += 256) {
            int l = l0 + tid;
            int kk = l >> 6, n = l & 63;
            int col = n0 + n;
            Ws[kk][n] = (col < Cout) ? w2[(size_t)(k0+kk)*Cout + col] : 0.f;
        }
        __syncthreads();
        #pragma unroll
        for (int kk = 0; kk < 16; kk++) {
            float4 a4 = *(const float4*)&As[kk][ty*4];
            float4 b4 = *(const float4*)&Ws[kk][tx*4];
            float a[4] = {a4.x, a4.y, a4.z, a4.w};
            float bb[4] = {b4.x, b4.y, b4.z, b4.w};
            #pragma unroll
            for (int qi = 0; qi < 4; qi++)
                #pragma unroll
                for (int qj = 0; qj < 4; qj++)
                    acc[qi][qj] += a[qi] * bb[qj];
        }
        __syncthreads();
    }
    #pragma unroll
    for (int qi = 0; qi < 4; qi++)
        #pragma unroll
        for (int qj = 0; qj < 4; qj++)
            Rs[ty*4+qi][tx*4+qj] = acc[qi][qj];
    __syncthreads();
    int pt0 = pt_s[0];
    for (int l = tid; l < 512; l += 256) {
        int pl = l >> 6, c = l & 63;
        int col = n0 + c;
        if (col < Cout) {
            float m = Rs[pl*8][c];
            #pragma unroll
            for (int r = 1; r < 8; r++) m = fmaxf(m, Rs[pl*8 + r][c]);
            out[(size_t)(pt0 + pl)*ldo + col] = m + b2[col];
        }
    }
}

// ---------------- tf32 tensor-core edge GEMM (conv3 only) -----------------
// 64 edges x 64 cols per block, 8 warps as 4(m) x 2(n); each warp 16x32 via
// 4 x m16n8k8 tf32 mma per k-step. conv3's output never feeds a kNN, so
// tf32 input rounding cannot flip any neighbor graph.
__global__ __launch_bounds__(256) void edge_gemm_tc_kernel(
    const float* __restrict__ uv, int ld,
    const float* __restrict__ w2, const float* __restrict__ b2,
    float* __restrict__ out, int ldo, int H, int Cout)
{
    __shared__ int pt_s[64], nb_s[64];
    __shared__ unsigned As[64][36];   // [row][k], K-panel = 32 (+4 pad)
    __shared__ unsigned Ws[32][72];   // [k][n], pad 72 -> conflict-free frags
    __shared__ float Rs[64][65];
    int tid = threadIdx.x;
    int e0 = blockIdx.x * 64;
    int n0 = blockIdx.y * 64;
    if (tid < 64) {
        int e = e0 + tid;
        int b = e / NEDGE_PB;
        int eb = e % NEDGE_PB;
        int i = eb / KNN, k = eb % KNN;
        int pt = b * NPTS + i;
        pt_s[tid] = pt;
        nb_s[tid] = b * NPTS + g_idx[pt*KNN + k];
    }
    __syncthreads();
    int lane = tid & 31, warp = tid >> 5;
    int wm = warp & 3, wn = warp >> 2;      // warp tile: rows wm*16, cols wn*32
    int g = lane >> 2, t4 = lane & 3;
    float d[4][4];
    #pragma unroll
    for (int a = 0; a < 4; a++)
        #pragma unroll
        for (int c = 0; c < 4; c++) d[a][c] = 0.f;

    for (int k0 = 0; k0 < H; k0 += 32) {
        // A tile: relu(u_i + v_j) -> tf32, 64 rows x 32 k (coalesced per warp)
        #pragma unroll
        for (int l0 = 0; l0 < 2048; l0 += 256) {
            int l = l0 + tid;
            int r = l >> 5, kk = l & 31;
            int h = k0 + kk;
            float a = uv[(size_t)pt_s[r]*ld + h] + uv[(size_t)nb_s[r]*ld + H + h];
            As[r][kk] = f2tf32(fmaxf(a, 0.f));
        }
        // W tile: 32 k x 64 cols -> tf32
        #pragma unroll
        for (int l0 = 0; l0 < 2048; l0 += 256) {
            int l = l0 + tid;
            int kk = l >> 6, n = l & 63;
            Ws[kk][n] = f2tf32(w2[(size_t)(k0 + kk)*Cout + n0 + n]);
        }
        __syncthreads();
        #pragma unroll
        for (int ks = 0; ks < 32; ks += 8) {
            unsigned a0 = As[wm*16 + g    ][ks + t4];
            unsigned a1 = As[wm*16 + g + 8][ks + t4];
            unsigned a2 = As[wm*16 + g    ][ks + t4 + 4];
            unsigned a3 = As[wm*16 + g + 8][ks + t4 + 4];
            #pragma unroll
            for (int ns = 0; ns < 4; ns++) {
                int n = wn*32 + ns*8 + g;
                unsigned b0 = Ws[ks + t4    ][n];
                unsigned b1 = Ws[ks + t4 + 4][n];
                asm volatile(
                    "mma.sync.aligned.m16n8k8.row.col.f32.tf32.tf32.f32 "
                    "{%0,%1,%2,%3}, {%4,%5,%6,%7}, {%8,%9}, {%0,%1,%2,%3};"
                    : "+f"(d[ns][0]), "+f"(d[ns][1]), "+f"(d[ns][2]), "+f"(d[ns][3])
                    : "r"(a0), "r"(a1), "r"(a2), "r"(a3), "r"(b0), "r"(b1));
            }
        }
        __syncthreads();
    }
    // accumulators -> Rs (m16n8 C-fragment layout)
    #pragma unroll
    for (int ns = 0; ns < 4; ns++) {
        int col = wn*32 + ns*8 + 2*t4;
        Rs[wm*16 + g    ][col    ] = d[ns][0];
        Rs[wm*16 + g    ][col + 1] = d[ns][1];
        Rs[wm*16 + g + 8][col    ] = d[ns][2];
        Rs[wm*16 + g + 8][col + 1] = d[ns][3];
    }
    __syncthreads();
    int pt0 = pt_s[0];
    for (int l = tid; l < 512; l += 256) {
        int pl = l >> 6, c = l & 63;
        int col = n0 + c;
        float m = Rs[pl*8][c];
        #pragma unroll
        for (int r = 1; r < 8; r++) m = fmaxf(m, Rs[pl*8 + r][c]);
        out[(size_t)(pt0 + pl)*ldo + col] = m + b2[col];
    }
}

// ---------------- global max pool over N ----------------------------------
__global__ void gmax_kernel() {
    int b = blockIdx.x, tid = threadIdx.x;
    int c = tid & 127, part = tid >> 7;
    __shared__ float sm[512];
    float m = -FLT_MAX;
    int n0 = part * (NPTS/4), n1 = n0 + NPTS/4;
    for (int n = n0; n < n1; n++)
        m = fmaxf(m, g_sf[(size_t)(b*NPTS + n)*128 + c]);
    sm[tid] = m;
    __syncthreads();
    if (tid < 128)
        g_gmax[b*128 + c] = fmaxf(fmaxf(sm[tid], sm[tid+128]),
                                  fmaxf(sm[tid+256], sm[tid+384]));
}

// ---------------- hg = g @ ec_w1[256:384] + ec_b1 -------------------------
__global__ void hg_kernel(const float* __restrict__ ecw1, const float* __restrict__ ecb1) {
    int b = blockIdx.x, h = threadIdx.x;
    float acc = ecb1[h];
    for (int c = 0; c < 128; c++)
        acc += g_gmax[b*128 + c] * ecw1[(size_t)(256 + c)*128 + h];
    g_hg[b*128 + h] = acc;
}

// ---------------- pair kernel ---------------------------------------------
__global__ __launch_bounds__(256) void pair_kernel(
    const float* __restrict__ ecw2, const float* __restrict__ ecb2,
    float* __restrict__ out)
{
    int tj = blockIdx.x, ti = blockIdx.y, b = blockIdx.z;
    if (ti > tj) return;
    int i0 = ti * 64, j0 = tj * 64;
    __shared__ __align__(16) float As[32][68], Bs[32][68];
    __shared__ float Ww[32];
    int tid = threadIdx.x, tx = tid % 16, ty = tid / 16;
    float acc[4][4] = {};
    for (int h0 = 0; h0 < 128; h0 += 32) {
        #pragma unroll
        for (int l0 = 0; l0 < 2048; l0 += 256) {
            int l = l0 + tid;
            int r = l >> 5, kk = l & 31;
            int ii = i0 + r, jj = j0 + r;
            As[kk][r] = (ii < NPTS)
                ? g_hi[(size_t)(b*NPTS + ii)*128 + h0 + kk] + g_hg[b*128 + h0 + kk]
                : 0.f;
            Bs[kk][r] = (jj < NPTS)
                ? g_hj[(size_t)(b*NPTS + jj)*128 + h0 + kk]
                : 0.f;
        }
        if (tid < 32) Ww[tid] = ecw2[h0 + tid];
        __syncthreads();
        #pragma unroll
        for (int kk = 0; kk < 32; kk++) {
            float w = Ww[kk];
            float4 a4 = *(const float4*)&As[kk][ty*4];
            float4 b4 = *(const float4*)&Bs[kk][tx*4];
            float a[4] = {a4.x, a4.y, a4.z, a4.w};
            float bb[4] = {b4.x, b4.y, b4.z, b4.w};
            #pragma unroll
            for (int qi = 0; qi < 4; qi++)
                #pragma unroll
                for (int qj = 0; qj < 4; qj++)
                    acc[qi][qj] += fmaxf(a[qi] + bb[qj], 0.f) * w;
        }
        __syncthreads();
    }
    float bias = ecb2[0];
    #pragma unroll
    for (int qi = 0; qi < 4; qi++) {
        int i = i0 + ty*4 + qi;
        #pragma unroll
        for (int qj = 0; qj < 4; qj++) {
            int j = j0 + tx*4 + qj;
            if (j < NPTS && i < j) {
                float val = acc[qi][qj] + bias;
                int p = i*(2*NPTS - i - 1)/2 + (j - i - 1);
                out[(size_t)b*PAIRS + p] = 1.f / (1.f + __expf(-val));
                out[(size_t)(BATCH + b)*PAIRS + p] = val;
            }
        }
    }
}

// ---------------- host side -----------------------------------------------
static void run_conv(const float* xin, int lda, int C, int H, int Cout, int outoff,
                     const float* w1, const float* b1, const float* w2, const float* b2,
                     float* dxcat, float* duv, float* dwcat, float* dbcat)
{
    sq_kernel<<<(NROWS + 7)/8, 256>>>(xin, lda, C);
    dim3 gd2((NPTS + 63)/64, (NPTS + 63)/64, BATCH);
    d2_kernel<<<gd2, 256>>>(xin, lda, C);
    topk_kernel<<<NROWS, 128>>>();
    int H2 = 2 * H;
    int tot = C * H2;
    wprep_kernel<<<(tot + 255)/256, 256>>>(w1, b1, C, H);
    // uv = x @ wcat + bcat  (M=NROWS, K=C, N=2H)
    dim3 ggu((NROWS + 63)/64, (H2 + 63)/64);
    gemm_kernel<<<ggu, 256>>>(xin, lda, dwcat, dbcat, duv, H2, NROWS, C, H2, 0);
    dim3 ge(NEDGES/64, (Cout + 63)/64);
    if (Cout == 512) {
        edge_gemm_tc_kernel<<<ge, 256>>>(duv, H2, w2, b2, dxcat + outoff, XCAT, H, Cout);
    } else {
        edge_gemm_kernel<<<ge, 256>>>(duv, H2, w2, b2, dxcat + outoff, XCAT, H, Cout);
    }
}

extern "C" void kernel_launch(void* const* d_in, const int* in_sizes, int n_in,
                              void* d_out, int out_size)
{
    const float* pos   = (const float*)d_in[0];
    const float* c1w1  = (const float*)d_in[1];
    const float* c1b1  = (const float*)d_in[2];
    const float* c1w2  = (const float*)d_in[3];
    const float* c1b2  = (const float*)d_in[4];
    const float* c2w1  = (const float*)d_in[5];
    const float* c2b1  = (const float*)d_in[6];
    const float* c2w2  = (const float*)d_in[7];
    const float* c2b2  = (const float*)d_in[8];
    const float* c3w1  = (const float*)d_in[9];
    const float* c3b1  = (const float*)d_in[10];
    const float* c3w2  = (const float*)d_in[11];
    const float* c3b2  = (const float*)d_in[12];
    const float* smw1  = (const float*)d_in[13];
    const float* smb1  = (const float*)d_in[14];
    const float* smw2  = (const float*)d_in[15];
    const float* smb2  = (const float*)d_in[16];
    const float* ecw1  = (const float*)d_in[17];
    const float* ecb1  = (const float*)d_in[18];
    const float* ecw2  = (const float*)d_in[19];
    const float* ecb2  = (const float*)d_in[20];
    float* out = (float*)d_out;

    float *dxcat, *duv, *dwcat, *dbcat, *dh1, *dsf, *dhi, *dhj;
    cudaGetSymbolAddress((void**)&dxcat, g_xcat);
    cudaGetSymbolAddress((void**)&duv,   g_uv);
    cudaGetSymbolAddress((void**)&dwcat, g_wcat);
    cudaGetSymbolAddress((void**)&dbcat, g_bcat);
    cudaGetSymbolAddress((void**)&dh1,   g_h1);
    cudaGetSymbolAddress((void**)&dsf,   g_sf);
    cudaGetSymbolAddress((void**)&dhi,   g_hi);
    cudaGetSymbolAddress((void**)&dhj,   g_hj);

    // Three dynamic edge convs, outputs concatenated into g_xcat
    run_conv(pos,        3,    3,   16,  32,   0,   c1w1, c1b1, c1w2, c1b2, dxcat, duv, dwcat, dbcat);
    run_conv(dxcat + 0,  XCAT, 32,  64,  128, 32,   c2w1, c2b1, c2w2, c2b2, dxcat, duv, dwcat, dbcat);
    run_conv(dxcat + 32, XCAT, 128, 256, 512, 160,  c3w1, c3b1, c3w2, c3b2, dxcat, duv, dwcat, dbcat);

    // sf = MLP(xcat): 672 -> 256 (relu) -> 128
    {
        dim3 g1((NROWS + 63)/64, (256 + 63)/64);
        gemm_kernel<<<g1, 256>>>(dxcat, XCAT, smw1, smb1, dh1, 256, NROWS, XCAT, 256, 1);
        dim3 g2((NROWS + 63)/64, (128 + 63)/64);
        gemm_kernel<<<g2, 256>>>(dh1, 256, smw2, smb2, dsf, 128, NROWS, 256, 128, 0);
    }

    // global max pool
    gmax_kernel<<<BATCH, 512>>>();

    // hi = sf @ ec_w1[:128], hj = sf @ ec_w1[128:256], hg = g @ ec_w1[256:] + b1
    {
        dim3 g3((NROWS + 63)/64, (128 + 63)/64);
        gemm_kernel<<<g3, 256>>>(dsf, 128, ecw1,           (const float*)nullptr, dhi, 128, NROWS, 128, 128, 0);
        gemm_kernel<<<g3, 256>>>(dsf, 128, ecw1 + 128*128, (const float*)nullptr, dhj, 128, NROWS, 128, 128, 0);
        hg_kernel<<<BATCH, 128>>>(ecw1, ecb1);
    }

    // pairwise output
    {
        dim3 gp((NPTS + 63)/64, (NPTS + 63)/64, BATCH);
        pair_kernel<<<gp, 256>>>(ecw2, ecb2, out);
    }
    (void)in_sizes; (void)n_in; (void)out_size;
}